// round 14
// baseline (speedup 1.0000x reference)
#include <cuda_runtime.h>
#include <math.h>
#include <cstdint>

#define NN 1000
#define FF 64
#define BB 16
#define TT 12
#define KK 5
#define CC 10
#define EE 16000
#define SS (BB*TT)          /* 192 snapshots */
#define RR (SS*NN)          /* 192000 rows   */
#define KDIM 576            /* 9 terms * 64  */
#define GDIM 128            /* 2 gates * 64  */
#define PERB (TT*NN*FF)     /* 768000        */
#define NCHUNK 1500
#define CHSZ 512

// GEMM tiling
#define KC    48
#define NCH   12
#define SAS   52            /* smem row stride (floats), 16B aligned */
#define TILEF (128*SAS)     /* 6656 floats per tile */
#define GSMEM (TILEF*4*4)   /* double-buffered A+B: 106496 bytes */

// cheb persistent kernel smem: edge lists (forces 1 CTA/SM, keeps L1 for planes)
#define CSMEM (EE*8 + EE*4) /* 192000 bytes */

// ---------------- scratch (static device globals; no runtime alloc) ----------
__device__ float g_TX[RR * KDIM];        // 442 MB: 9 Chebyshev term blocks
__device__ float g_HLN[RR * FF];         // 49 MB: layernormed hidden
__device__ float g_Wt[GDIM * KDIM];      // fused weights, transposed
__device__ int   g_deg_out[NN], g_deg_in[NN];
__device__ float g_inv_out[NN], g_inv_in[NN];
__device__ int   g_in_ptr[NN + 1], g_out_ptr[NN + 1];
__device__ int2  g_in_ew[EE];            // {src_idx, weight-bits} packed
__device__ int   g_out_idx[EE];
__device__ int   g_cnt_in[NN], g_cnt_out[NN];
__device__ float g_part[NCHUNK * 160];

// ---------------- graph preprocessing ----------------------------------------
__global__ void k_zero() {
    int i = blockIdx.x * blockDim.x + threadIdx.x;
    if (i < NN) { g_deg_out[i] = 0; g_deg_in[i] = 0; g_cnt_in[i] = 0; g_cnt_out[i] = 0; }
}
__global__ void k_count(const int* __restrict__ ei) {
    int e = blockIdx.x * blockDim.x + threadIdx.x;
    if (e < EE) {
        atomicAdd(&g_deg_out[ei[e]], 1);
        atomicAdd(&g_deg_in[ei[EE + e]], 1);
    }
}
// parallel exclusive scan (1024 threads, Hillis-Steele in smem)
__global__ void __launch_bounds__(1024) k_scan() {
    __shared__ int sa[1024], sb[1024];
    int t = threadIdx.x;
    int a = (t < NN) ? g_deg_in[t]  : 0;
    int b = (t < NN) ? g_deg_out[t] : 0;
    sa[t] = a; sb[t] = b;
    __syncthreads();
    for (int o = 1; o < 1024; o <<= 1) {
        int va = (t >= o) ? sa[t - o] : 0;
        int vb = (t >= o) ? sb[t - o] : 0;
        __syncthreads();
        sa[t] += va; sb[t] += vb;
        __syncthreads();
    }
    if (t < NN) {
        g_in_ptr[t]  = sa[t] - a;       // exclusive
        g_out_ptr[t] = sb[t] - b;
        g_inv_in[t]  = 1.0f / (float)a;
        g_inv_out[t] = 1.0f / (float)b;
    }
    if (t == 0) { g_in_ptr[NN] = EE; g_out_ptr[NN] = EE; }
}
__global__ void k_fill(const int* __restrict__ ei) {
    int e = blockIdx.x * blockDim.x + threadIdx.x;
    if (e < EE) {
        int s = ei[e], d = ei[EE + e];
        int p = atomicAdd(&g_cnt_in[d], 1);
        g_in_ew[g_in_ptr[d] + p] = make_int2(s, __float_as_int(g_inv_out[s]));
        int q = atomicAdd(&g_cnt_out[s], 1);
        g_out_idx[g_out_ptr[s] + q] = d;
    }
}

// ---------------- fused weight build (transposed: g_Wt[n][k]) -----------------
__global__ void k_wcat(const float* __restrict__ Wz, const float* __restrict__ Wh) {
    int i = blockIdx.x * blockDim.x + threadIdx.x;
    if (i >= KDIM * GDIM) return;
    int col  = i / KDIM, krow = i % KDIM;
    int term = krow / FF, ic = krow % FF;
    int gate = col / FF,  oc = col % FF;
    const float* W = (gate == 0) ? Wz : Wh;
    float v;
    if (term == 0)
        v = W[((0 * KK + 0) * 2 * FF + ic) * FF + oc] +
            W[((1 * KK + 0) * 2 * FF + ic) * FF + oc];
    else if (term <= 4)
        v = W[((0 * KK + term) * 2 * FF + ic) * FF + oc];
    else
        v = W[((1 * KK + (term - 4)) * 2 * FF + ic) * FF + oc];
    g_Wt[col * KDIM + krow] = v;
}

// ===== persistent Chebyshev: CTA = (snapshot, feature-half), L1-resident =====
// Phase-separated per direction so the gather working set per phase is one
// 128 KB plane (1000 nodes x 128B line, fully used). Edge lists in smem.
__global__ void __launch_bounds__(512) k_chebp(const float* __restrict__ x) {
    extern __shared__ char csp[];
    int2* sew = (int2*)csp;                 // 128000 B: in-edges {src, w}
    int*  soi = (int*)(csp + EE * 8);       //  64000 B: out-edge dst idx
    const int s = blockIdx.x >> 1, half = blockIdx.x & 1;
    const int tid = threadIdx.x;
    const int w = tid >> 5;                 // warp 0..15
    const int nsub = (tid >> 3) & 3;        // node-in-warp 0..3
    const int fq = tid & 7;                 // feature quad 0..7
    const int col = half * 32 + fq * 4;
    float* txs = g_TX + (size_t)s * NN * KDIM;

    for (int i = tid; i < EE; i += 512) { sew[i] = g_in_ew[i]; soi[i] = g_out_idx[i]; }
    __syncthreads();

    // ---- step 1: both directions gather the same x plane; write term0 ----
    const float* xs = x + (size_t)s * NN * FF + col;
    for (int p = 0; p < 16; p++) {
        int n = p * 64 + w * 4 + nsub;
        if (n >= NN) break;
        float4 aO = make_float4(0.f, 0.f, 0.f, 0.f);
        float4 aI = make_float4(0.f, 0.f, 0.f, 0.f);
        int jb = g_in_ptr[n], je = g_in_ptr[n + 1];
#pragma unroll 2
        for (int j = jb; j < je; j++) {
            int2 ew = sew[j];
            float wt = __int_as_float(ew.y);
            float4 v = *(const float4*)(xs + (size_t)ew.x * FF);
            aO.x = fmaf(wt, v.x, aO.x); aO.y = fmaf(wt, v.y, aO.y);
            aO.z = fmaf(wt, v.z, aO.z); aO.w = fmaf(wt, v.w, aO.w);
        }
        jb = g_out_ptr[n]; je = g_out_ptr[n + 1];
#pragma unroll 2
        for (int j = jb; j < je; j++) {
            float4 v = *(const float4*)(xs + (size_t)soi[j] * FF);
            aI.x += v.x; aI.y += v.y; aI.z += v.z; aI.w += v.w;
        }
        float wi = g_inv_in[n];
        aI.x *= wi; aI.y *= wi; aI.z *= wi; aI.w *= wi;
        float4 x0 = *(const float4*)(xs + (size_t)n * FF);
        float* rp = txs + (size_t)n * KDIM + col;
        *(float4*)(rp)          = x0;   // term 0
        *(float4*)(rp + FF)     = aO;   // Tx1o
        *(float4*)(rp + 5 * FF) = aI;   // Tx1i
    }
    __syncthreads();

#pragma unroll
    for (int st = 1; st < 4; st++) {
        const int so = st, si = st + 4, to = st + 1, ti = st + 5, sub = st - 1;
        // ---- phase A: out-direction (gather so-plane only) ----
        const float* bO = txs + so * FF + col;
        for (int p = 0; p < 16; p++) {
            int n = p * 64 + w * 4 + nsub;
            if (n >= NN) break;
            float4 aO = make_float4(0.f, 0.f, 0.f, 0.f);
            int jb = g_in_ptr[n], je = g_in_ptr[n + 1];
#pragma unroll 2
            for (int j = jb; j < je; j++) {
                int2 ew = sew[j];
                float wt = __int_as_float(ew.y);
                float4 v = *(const float4*)(bO + (size_t)ew.x * KDIM);
                aO.x = fmaf(wt, v.x, aO.x); aO.y = fmaf(wt, v.y, aO.y);
                aO.z = fmaf(wt, v.z, aO.z); aO.w = fmaf(wt, v.w, aO.w);
            }
            float* rp = txs + (size_t)n * KDIM + col;
            float4 t0 = *(const float4*)(rp + sub * FF);
            aO.x = fmaf(2.f, aO.x, -t0.x); aO.y = fmaf(2.f, aO.y, -t0.y);
            aO.z = fmaf(2.f, aO.z, -t0.z); aO.w = fmaf(2.f, aO.w, -t0.w);
            *(float4*)(rp + to * FF) = aO;
        }
        __syncthreads();
        // ---- phase B: in-direction (gather si-plane only) ----
        const float* bI = txs + si * FF + col;
        for (int p = 0; p < 16; p++) {
            int n = p * 64 + w * 4 + nsub;
            if (n >= NN) break;
            float4 aI = make_float4(0.f, 0.f, 0.f, 0.f);
            int jb = g_out_ptr[n], je = g_out_ptr[n + 1];
#pragma unroll 2
            for (int j = jb; j < je; j++) {
                float4 v = *(const float4*)(bI + (size_t)soi[j] * KDIM);
                aI.x += v.x; aI.y += v.y; aI.z += v.z; aI.w += v.w;
            }
            float wi = g_inv_in[n];
            float* rp = txs + (size_t)n * KDIM + col;
            float4 t0 = *(const float4*)(rp + sub * FF);
            aI.x = fmaf(2.f, aI.x * wi, -t0.x); aI.y = fmaf(2.f, aI.y * wi, -t0.y);
            aI.z = fmaf(2.f, aI.z * wi, -t0.z); aI.w = fmaf(2.f, aI.w * wi, -t0.w);
            *(float4*)(rp + ti * FF) = aI;
        }
        __syncthreads();
    }
}

// ================= tf32 warp-MMA GEMM, double-buffered, fused epilogue ========
__device__ __forceinline__ uint32_t f2tf32(float f) {
    uint32_t r; asm("cvt.rna.tf32.f32 %0, %1;" : "=r"(r) : "f"(f)); return r;
}
__device__ __forceinline__ float4 cvt4(float4 v) {
    float4 r;
    r.x = __uint_as_float(f2tf32(v.x)); r.y = __uint_as_float(f2tf32(v.y));
    r.z = __uint_as_float(f2tf32(v.z)); r.w = __uint_as_float(f2tf32(v.w));
    return r;
}
#define MMA_TF32(c, a0, a1, a2, a3, b0, b1) \
    asm volatile("mma.sync.aligned.m16n8k8.row.col.f32.tf32.tf32.f32 " \
        "{%0,%1,%2,%3}, {%4,%5,%6,%7}, {%8,%9}, {%0,%1,%2,%3};" \
        : "+f"((c)[0]), "+f"((c)[1]), "+f"((c)[2]), "+f"((c)[3]) \
        : "r"(a0), "r"(a1), "r"(a2), "r"(a3), "r"(b0), "r"(b1))

__global__ void __launch_bounds__(256) k_gemm_mma(
    const float* __restrict__ bz, const float* __restrict__ bh,
    const float* __restrict__ lng, const float* __restrict__ lnb)
{
    extern __shared__ float sm[];
    const int tid = threadIdx.x, wid = tid >> 5, lane = tid & 31;
    const int mg = wid >> 1, ng = wid & 1, g = lane >> 2, qc = lane & 3;
    const int row0 = blockIdx.x * 128;

    float acc[2][8][4];
#pragma unroll
    for (int a = 0; a < 2; a++)
#pragma unroll
        for (int j = 0; j < 8; j++)
#pragma unroll
            for (int d = 0; d < 4; d++) acc[a][j][d] = 0.f;

    const int rr = tid >> 1, hh = tid & 1;
    const float* Ag = g_TX + (size_t)(row0 + rr) * KDIM + hh * 24;
    const float* Bg = g_Wt + (size_t)rr * KDIM + hh * 24;
    float4 pa[6], pb[6];

#pragma unroll
    for (int i = 0; i < 6; i++) {
        pa[i] = *(const float4*)(Ag + i * 4);
        pb[i] = *(const float4*)(Bg + i * 4);
    }
#pragma unroll
    for (int i = 0; i < 6; i++) {
        *(float4*)&sm[rr * SAS + hh * 24 + i * 4]          = cvt4(pa[i]);
        *(float4*)&sm[TILEF + rr * SAS + hh * 24 + i * 4]  = cvt4(pb[i]);
    }
#pragma unroll
    for (int i = 0; i < 6; i++) {
        pa[i] = *(const float4*)(Ag + KC + i * 4);
        pb[i] = *(const float4*)(Bg + KC + i * 4);
    }
    __syncthreads();

#pragma unroll 1
    for (int ch = 0; ch < NCH; ch++) {
        const int cur = ch & 1, nxt = cur ^ 1;
        float* sA = sm + cur * 2 * TILEF;
        float* sB = sA + TILEF;
        if (ch + 1 < NCH) {
            float* dA = sm + nxt * 2 * TILEF;
#pragma unroll
            for (int i = 0; i < 6; i++) {
                *(float4*)&dA[rr * SAS + hh * 24 + i * 4]         = cvt4(pa[i]);
                *(float4*)&dA[TILEF + rr * SAS + hh * 24 + i * 4] = cvt4(pb[i]);
            }
        }
        if (ch + 2 < NCH) {
#pragma unroll
            for (int i = 0; i < 6; i++) {
                pa[i] = *(const float4*)(Ag + (ch + 2) * KC + i * 4);
                pb[i] = *(const float4*)(Bg + (ch + 2) * KC + i * 4);
            }
        }
#pragma unroll
        for (int ks = 0; ks < 6; ks++) {
            const int k0 = ks * 8;
            uint32_t a[2][4];
#pragma unroll
            for (int mt = 0; mt < 2; mt++) {
                int r = mg * 32 + mt * 16 + g;
                a[mt][0] = __float_as_uint(sA[r * SAS + k0 + qc]);
                a[mt][1] = __float_as_uint(sA[(r + 8) * SAS + k0 + qc]);
                a[mt][2] = __float_as_uint(sA[r * SAS + k0 + qc + 4]);
                a[mt][3] = __float_as_uint(sA[(r + 8) * SAS + k0 + qc + 4]);
            }
#pragma unroll
            for (int j = 0; j < 8; j++) {
                int ntg = ((j >> 2) << 3) + (ng << 2) + (j & 3);
                int col = ntg * 8 + g;
                uint32_t b0 = __float_as_uint(sB[col * SAS + k0 + qc]);
                uint32_t b1 = __float_as_uint(sB[col * SAS + k0 + qc + 4]);
                MMA_TF32(acc[0][j], a[0][0], a[0][1], a[0][2], a[0][3], b0, b1);
                MMA_TF32(acc[1][j], a[1][0], a[1][1], a[1][2], a[1][3], b0, b1);
            }
        }
        __syncthreads();
    }

    if (tid < 64) {
        sm[512 + tid] = bz[tid];
        sm[576 + tid] = bh[tid];
        sm[640 + tid] = lng[tid];
        sm[704 + tid] = lnb[tid];
    }
    __syncthreads();

    float hc[2][2][8];
#pragma unroll
    for (int mt = 0; mt < 2; mt++)
#pragma unroll
        for (int half = 0; half < 2; half++) {
            float sv = 0.f, sq = 0.f;
#pragma unroll
            for (int j = 0; j < 4; j++)
#pragma unroll
                for (int d = 0; d < 2; d++) {
                    int fz = ((ng << 2) + j) * 8 + qc * 2 + d;
                    float zl = acc[mt][j][half * 2 + d]     + sm[512 + fz];
                    float hl = acc[mt][j + 4][half * 2 + d] + sm[576 + fz];
                    float z  = 1.f / (1.f + __expf(-zl));
                    float v  = fmaxf((1.f - z) * tanhf(hl), 0.f);
                    hc[mt][half][j * 2 + d] = v;
                    sv += v; sq += v * v;
                }
            sv += __shfl_xor_sync(0xffffffffu, sv, 1);
            sq += __shfl_xor_sync(0xffffffffu, sq, 1);
            sv += __shfl_xor_sync(0xffffffffu, sv, 2);
            sq += __shfl_xor_sync(0xffffffffu, sq, 2);
            if (qc == 0) {
                int r = mg * 32 + mt * 16 + half * 8 + g;
                *(float2*)&sm[(r * 2 + ng) * 2] = make_float2(sv, sq);
            }
        }
    __syncthreads();

#pragma unroll
    for (int mt = 0; mt < 2; mt++)
#pragma unroll
        for (int half = 0; half < 2; half++) {
            int r = mg * 32 + mt * 16 + half * 8 + g;
            float2 p0 = *(float2*)&sm[(r * 2 + 0) * 2];
            float2 p1 = *(float2*)&sm[(r * 2 + 1) * 2];
            float mu = (p0.x + p1.x) * (1.f / 64.f);
            float var = (p0.y + p1.y) * (1.f / 64.f) - mu * mu;
            float rstd = rsqrtf(var + 1e-5f);
            float* op = g_HLN + (size_t)(row0 + r) * FF;
#pragma unroll
            for (int j = 0; j < 4; j++) {
                int f0 = ((ng << 2) + j) * 8 + qc * 2;
                float2 o;
                o.x = (hc[mt][half][j * 2]     - mu) * rstd * sm[640 + f0]     + sm[704 + f0];
                o.y = (hc[mt][half][j * 2 + 1] - mu) * rstd * sm[640 + f0 + 1] + sm[704 + f0 + 1];
                *(float2*)(op + f0) = o;
            }
        }
}

// ---------------- final linear: out[b,c] = <HLN[b,:], lin_w[c,:]> + lin_b -----
__global__ void k_lin1(const float* __restrict__ w) {
    int chunk = blockIdx.x;
    int tid = threadIdx.x;
    int b = tid / CC, c = tid % CC;
    const float4* hp = (const float4*)(g_HLN + b * PERB + chunk * CHSZ);
    const float4* wp = (const float4*)(w     + c * PERB + chunk * CHSZ);
    float acc = 0.f;
#pragma unroll 4
    for (int i = 0; i < CHSZ / 4; i++) {
        float4 hv = hp[i], wv = wp[i];
        acc += hv.x * wv.x + hv.y * wv.y + hv.z * wv.z + hv.w * wv.w;
    }
    g_part[chunk * 160 + tid] = acc;
}
__global__ void __launch_bounds__(256) k_lin2(const float* __restrict__ lb, float* __restrict__ out) {
    __shared__ float red[256];
    int bc = blockIdx.x, t = threadIdx.x;
    float acc = 0.f;
    for (int ch = t; ch < NCHUNK; ch += 256) acc += g_part[ch * 160 + bc];
    red[t] = acc; __syncthreads();
#pragma unroll
    for (int o = 128; o; o >>= 1) {
        if (t < o) red[t] += red[t + o];
        __syncthreads();
    }
    if (t == 0) {
        int b = bc / CC, c = bc % CC;
        out[b * CC + c] = red[0] + lb[c];
    }
}

// ---------------- launch -------------------------------------------------------
extern "C" void kernel_launch(void* const* d_in, const int* in_sizes, int n_in,
                              void* d_out, int out_size) {
    const float* x    = (const float*)d_in[0];
    const int*   ei   = (const int*)  d_in[1];
    const float* Wz   = (const float*)d_in[2];
    const float* bz   = (const float*)d_in[3];
    // d_in[4], d_in[5] (W_r, b_r) are mathematically dead (h0 == 0)
    const float* Wh   = (const float*)d_in[6];
    const float* bh   = (const float*)d_in[7];
    const float* lng  = (const float*)d_in[8];
    const float* lnb  = (const float*)d_in[9];
    const float* lw   = (const float*)d_in[10];
    const float* lb   = (const float*)d_in[11];
    float* out = (float*)d_out;

    // idempotent, capture-safe, no static guards
    cudaFuncSetAttribute(k_chebp, cudaFuncAttributeMaxDynamicSharedMemorySize, CSMEM);
    cudaFuncSetAttribute(k_gemm_mma, cudaFuncAttributeMaxDynamicSharedMemorySize, GSMEM);

    k_zero<<<4, 256>>>();
    k_count<<<(EE + 255) / 256, 256>>>(ei);
    k_scan<<<1, 1024>>>();
    k_fill<<<(EE + 255) / 256, 256>>>(ei);
    k_wcat<<<(KDIM * GDIM + 255) / 256, 256>>>(Wz, Wh);

    k_chebp<<<SS * 2, 512, CSMEM>>>(x);    // all 4 Chebyshev steps, L1-resident

    k_gemm_mma<<<RR / 128, 256, GSMEM>>>(bz, bh, lng, lnb);

    k_lin1<<<NCHUNK, 160>>>(lw);
    k_lin2<<<160, 256>>>(lb, out);
}

// round 15
// speedup vs baseline: 1.5708x; 1.5708x over previous
#include <cuda_runtime.h>
#include <math.h>
#include <cstdint>

#define NN 1000
#define FF 64
#define BB 16
#define TT 12
#define KK 5
#define CC 10
#define EE 16000
#define SS (BB*TT)          /* 192 snapshots */
#define RR (SS*NN)          /* 192000 rows   */
#define KDIM 576            /* 9 terms * 64  */
#define GDIM 128            /* 2 gates * 64  */
#define PERB (TT*NN*FF)     /* 768000        */
#define NCHUNK 1500
#define CHSZ 512

// GEMM tiling
#define KC    48
#define NCH   12
#define SAS   52            /* smem row stride (floats), 16B aligned */
#define TILEF (128*SAS)     /* 6656 floats per tile */
#define GSMEM (TILEF*4*4)   /* double-buffered A+B: 106496 bytes */

// ---------------- scratch (static device globals; no runtime alloc) ----------
__device__ float g_TX[RR * KDIM];        // 442 MB: 9 Chebyshev term blocks
__device__ float g_HLN[RR * FF];         // 49 MB: layernormed hidden
__device__ float g_Wt[GDIM * KDIM];      // fused weights, transposed
__device__ int   g_deg_out[NN], g_deg_in[NN];
__device__ float g_inv_out[NN], g_inv_in[NN];
__device__ int   g_in_ptr[NN + 1], g_out_ptr[NN + 1];
__device__ int2  g_in_ew[EE];            // {src_idx, weight-bits} packed
__device__ int   g_out_idx[EE];
__device__ int   g_cnt_in[NN], g_cnt_out[NN];
__device__ float g_part[NCHUNK * 160];

// ---------------- graph preprocessing ----------------------------------------
__global__ void k_zero() {
    int i = blockIdx.x * blockDim.x + threadIdx.x;
    if (i < NN) { g_deg_out[i] = 0; g_deg_in[i] = 0; g_cnt_in[i] = 0; g_cnt_out[i] = 0; }
}
__global__ void k_count(const int* __restrict__ ei) {
    int e = blockIdx.x * blockDim.x + threadIdx.x;
    if (e < EE) {
        atomicAdd(&g_deg_out[ei[e]], 1);
        atomicAdd(&g_deg_in[ei[EE + e]], 1);
    }
}
// parallel exclusive scan (1024 threads, Hillis-Steele in smem)
__global__ void __launch_bounds__(1024) k_scan() {
    __shared__ int sa[1024], sb[1024];
    int t = threadIdx.x;
    int a = (t < NN) ? g_deg_in[t]  : 0;
    int b = (t < NN) ? g_deg_out[t] : 0;
    sa[t] = a; sb[t] = b;
    __syncthreads();
    for (int o = 1; o < 1024; o <<= 1) {
        int va = (t >= o) ? sa[t - o] : 0;
        int vb = (t >= o) ? sb[t - o] : 0;
        __syncthreads();
        sa[t] += va; sb[t] += vb;
        __syncthreads();
    }
    if (t < NN) {
        g_in_ptr[t]  = sa[t] - a;       // exclusive
        g_out_ptr[t] = sb[t] - b;
        g_inv_in[t]  = 1.0f / (float)a;
        g_inv_out[t] = 1.0f / (float)b;
    }
    if (t == 0) { g_in_ptr[NN] = EE; g_out_ptr[NN] = EE; }
}
__global__ void k_fill(const int* __restrict__ ei) {
    int e = blockIdx.x * blockDim.x + threadIdx.x;
    if (e < EE) {
        int s = ei[e], d = ei[EE + e];
        int p = atomicAdd(&g_cnt_in[d], 1);
        g_in_ew[g_in_ptr[d] + p] = make_int2(s, __float_as_int(g_inv_out[s]));
        int q = atomicAdd(&g_cnt_out[s], 1);
        g_out_idx[g_out_ptr[s] + q] = d;
    }
}

// ---------------- fused weight build (transposed: g_Wt[n][k]) -----------------
__global__ void k_wcat(const float* __restrict__ Wz, const float* __restrict__ Wh) {
    int i = blockIdx.x * blockDim.x + threadIdx.x;
    if (i >= KDIM * GDIM) return;
    int col  = i / KDIM, krow = i % KDIM;
    int term = krow / FF, ic = krow % FF;
    int gate = col / FF,  oc = col % FF;
    const float* W = (gate == 0) ? Wz : Wh;
    float v;
    if (term == 0)
        v = W[((0 * KK + 0) * 2 * FF + ic) * FF + oc] +
            W[((1 * KK + 0) * 2 * FF + ic) * FF + oc];
    else if (term <= 4)
        v = W[((0 * KK + term) * 2 * FF + ic) * FF + oc];
    else
        v = W[((1 * KK + (term - 4)) * 2 * FF + ic) * FF + oc];
    g_Wt[col * KDIM + krow] = v;
}

// ------- Chebyshev: warp = (node, snapshot-pair); lane = float4 x half --------
__global__ void __launch_bounds__(256) k_cheb1(const float* __restrict__ x) {
    const int W = blockIdx.x * 8 + threadIdx.y;
    const int node = W % NN, qp = W / NN;
    const int lane = threadIdx.x;
    const int half = lane >> 4, col = (lane & 15) * 4;
    const int s = qp * 2 + half;
    const float* xs = x + (size_t)s * NN * FF + col;

    float4 aO = make_float4(0.f, 0.f, 0.f, 0.f);
    int jb = g_in_ptr[node], je = g_in_ptr[node + 1];
#pragma unroll 4
    for (int j = jb; j < je; j++) {
        int2 ew = g_in_ew[j];
        float w = __int_as_float(ew.y);
        float4 v = *(const float4*)(xs + (size_t)ew.x * FF);
        aO.x = fmaf(w, v.x, aO.x); aO.y = fmaf(w, v.y, aO.y);
        aO.z = fmaf(w, v.z, aO.z); aO.w = fmaf(w, v.w, aO.w);
    }
    float4 aI = make_float4(0.f, 0.f, 0.f, 0.f);
    jb = g_out_ptr[node]; je = g_out_ptr[node + 1];
#pragma unroll 4
    for (int j = jb; j < je; j++) {
        float4 v = *(const float4*)(xs + (size_t)g_out_idx[j] * FF);
        aI.x += v.x; aI.y += v.y; aI.z += v.z; aI.w += v.w;
    }
    float wi = g_inv_in[node];
    aI.x *= wi; aI.y *= wi; aI.z *= wi; aI.w *= wi;

    float4 x0 = *(const float4*)(xs + (size_t)node * FF);
    float* rp = g_TX + ((size_t)s * NN + node) * KDIM + col;
    *(float4*)(rp)           = x0;    // term 0
    *(float4*)(rp + 1 * FF)  = aO;    // Tx1o
    *(float4*)(rp + 5 * FF)  = aI;    // Tx1i
}

__global__ void __launch_bounds__(256) k_cheb(int so, int si, int dro, int dri, int sub) {
    const int W = blockIdx.x * 8 + threadIdx.y;
    const int node = W % NN, qp = W / NN;
    const int lane = threadIdx.x;
    const int half = lane >> 4, col = (lane & 15) * 4;
    const int s = qp * 2 + half;
    const size_t sb = (size_t)s * NN * KDIM;
    const float* bO = g_TX + sb + so * FF + col;
    const float* bI = g_TX + sb + si * FF + col;

    float4 aO = make_float4(0.f, 0.f, 0.f, 0.f);
    int jb = g_in_ptr[node], je = g_in_ptr[node + 1];
#pragma unroll 4
    for (int j = jb; j < je; j++) {
        int2 ew = g_in_ew[j];
        float w = __int_as_float(ew.y);
        float4 v = *(const float4*)(bO + (size_t)ew.x * KDIM);
        aO.x = fmaf(w, v.x, aO.x); aO.y = fmaf(w, v.y, aO.y);
        aO.z = fmaf(w, v.z, aO.z); aO.w = fmaf(w, v.w, aO.w);
    }
    float4 aI = make_float4(0.f, 0.f, 0.f, 0.f);
    jb = g_out_ptr[node]; je = g_out_ptr[node + 1];
#pragma unroll 4
    for (int j = jb; j < je; j++) {
        float4 v = *(const float4*)(bI + (size_t)g_out_idx[j] * KDIM);
        aI.x += v.x; aI.y += v.y; aI.z += v.z; aI.w += v.w;
    }
    float wi = g_inv_in[node];

    float* rp = g_TX + sb + (size_t)node * KDIM + col;
    float4 t0 = *(const float4*)(rp + sub * FF);
    aO.x = fmaf(2.f, aO.x, -t0.x); aO.y = fmaf(2.f, aO.y, -t0.y);
    aO.z = fmaf(2.f, aO.z, -t0.z); aO.w = fmaf(2.f, aO.w, -t0.w);
    aI.x = fmaf(2.f, aI.x * wi, -t0.x); aI.y = fmaf(2.f, aI.y * wi, -t0.y);
    aI.z = fmaf(2.f, aI.z * wi, -t0.z); aI.w = fmaf(2.f, aI.w * wi, -t0.w);
    *(float4*)(rp + dro * FF) = aO;
    *(float4*)(rp + dri * FF) = aI;
}

// ================= tf32 warp-MMA GEMM, double-buffered, fused epilogue ========
__device__ __forceinline__ uint32_t f2tf32(float f) {
    uint32_t r; asm("cvt.rna.tf32.f32 %0, %1;" : "=r"(r) : "f"(f)); return r;
}
__device__ __forceinline__ float4 cvt4(float4 v) {
    float4 r;
    r.x = __uint_as_float(f2tf32(v.x)); r.y = __uint_as_float(f2tf32(v.y));
    r.z = __uint_as_float(f2tf32(v.z)); r.w = __uint_as_float(f2tf32(v.w));
    return r;
}
#define MMA_TF32(c, a0, a1, a2, a3, b0, b1) \
    asm volatile("mma.sync.aligned.m16n8k8.row.col.f32.tf32.tf32.f32 " \
        "{%0,%1,%2,%3}, {%4,%5,%6,%7}, {%8,%9}, {%0,%1,%2,%3};" \
        : "+f"((c)[0]), "+f"((c)[1]), "+f"((c)[2]), "+f"((c)[3]) \
        : "r"(a0), "r"(a1), "r"(a2), "r"(a3), "r"(b0), "r"(b1))

__global__ void __launch_bounds__(256, 2) k_gemm_mma(
    const float* __restrict__ bz, const float* __restrict__ bh,
    const float* __restrict__ lng, const float* __restrict__ lnb)
{
    extern __shared__ float sm[];
    const int tid = threadIdx.x, wid = tid >> 5, lane = tid & 31;
    const int mg = wid >> 1, ng = wid & 1, g = lane >> 2, qc = lane & 3;
    const int row0 = blockIdx.x * 128;

    float acc[2][8][4];
#pragma unroll
    for (int a = 0; a < 2; a++)
#pragma unroll
        for (int j = 0; j < 8; j++)
#pragma unroll
            for (int d = 0; d < 4; d++) acc[a][j][d] = 0.f;

    const int rr = tid >> 1, hh = tid & 1;
    const float* Ag = g_TX + (size_t)(row0 + rr) * KDIM + hh * 24;
    const float* Bg = g_Wt + (size_t)rr * KDIM + hh * 24;
    float4 pa[6], pb[6];

#pragma unroll
    for (int i = 0; i < 6; i++) {
        pa[i] = *(const float4*)(Ag + i * 4);
        pb[i] = *(const float4*)(Bg + i * 4);
    }
#pragma unroll
    for (int i = 0; i < 6; i++) {
        *(float4*)&sm[rr * SAS + hh * 24 + i * 4]          = cvt4(pa[i]);
        *(float4*)&sm[TILEF + rr * SAS + hh * 24 + i * 4]  = cvt4(pb[i]);
    }
#pragma unroll
    for (int i = 0; i < 6; i++) {
        pa[i] = *(const float4*)(Ag + KC + i * 4);
        pb[i] = *(const float4*)(Bg + KC + i * 4);
    }
    __syncthreads();

#pragma unroll 1
    for (int ch = 0; ch < NCH; ch++) {
        const int cur = ch & 1, nxt = cur ^ 1;
        float* sA = sm + cur * 2 * TILEF;
        float* sB = sA + TILEF;
        if (ch + 1 < NCH) {
            float* dA = sm + nxt * 2 * TILEF;
#pragma unroll
            for (int i = 0; i < 6; i++) {
                *(float4*)&dA[rr * SAS + hh * 24 + i * 4]         = cvt4(pa[i]);
                *(float4*)&dA[TILEF + rr * SAS + hh * 24 + i * 4] = cvt4(pb[i]);
            }
        }
        if (ch + 2 < NCH) {
#pragma unroll
            for (int i = 0; i < 6; i++) {
                pa[i] = *(const float4*)(Ag + (ch + 2) * KC + i * 4);
                pb[i] = *(const float4*)(Bg + (ch + 2) * KC + i * 4);
            }
        }
#pragma unroll
        for (int ks = 0; ks < 6; ks++) {
            const int k0 = ks * 8;
            uint32_t a[2][4];
#pragma unroll
            for (int mt = 0; mt < 2; mt++) {
                int r = mg * 32 + mt * 16 + g;
                a[mt][0] = __float_as_uint(sA[r * SAS + k0 + qc]);
                a[mt][1] = __float_as_uint(sA[(r + 8) * SAS + k0 + qc]);
                a[mt][2] = __float_as_uint(sA[r * SAS + k0 + qc + 4]);
                a[mt][3] = __float_as_uint(sA[(r + 8) * SAS + k0 + qc + 4]);
            }
#pragma unroll
            for (int j = 0; j < 8; j++) {
                int ntg = ((j >> 2) << 3) + (ng << 2) + (j & 3);
                int col = ntg * 8 + g;
                uint32_t b0 = __float_as_uint(sB[col * SAS + k0 + qc]);
                uint32_t b1 = __float_as_uint(sB[col * SAS + k0 + qc + 4]);
                MMA_TF32(acc[0][j], a[0][0], a[0][1], a[0][2], a[0][3], b0, b1);
                MMA_TF32(acc[1][j], a[1][0], a[1][1], a[1][2], a[1][3], b0, b1);
            }
        }
        __syncthreads();
    }

    if (tid < 64) {
        sm[512 + tid] = bz[tid];
        sm[576 + tid] = bh[tid];
        sm[640 + tid] = lng[tid];
        sm[704 + tid] = lnb[tid];
    }
    __syncthreads();

    float hc[2][2][8];
#pragma unroll
    for (int mt = 0; mt < 2; mt++)
#pragma unroll
        for (int half = 0; half < 2; half++) {
            float sv = 0.f, sq = 0.f;
#pragma unroll
            for (int j = 0; j < 4; j++)
#pragma unroll
                for (int d = 0; d < 2; d++) {
                    int fz = ((ng << 2) + j) * 8 + qc * 2 + d;
                    float zl = acc[mt][j][half * 2 + d]     + sm[512 + fz];
                    float hl = acc[mt][j + 4][half * 2 + d] + sm[576 + fz];
                    float z  = 1.f / (1.f + __expf(-zl));
                    float v  = fmaxf((1.f - z) * tanhf(hl), 0.f);
                    hc[mt][half][j * 2 + d] = v;
                    sv += v; sq += v * v;
                }
            sv += __shfl_xor_sync(0xffffffffu, sv, 1);
            sq += __shfl_xor_sync(0xffffffffu, sq, 1);
            sv += __shfl_xor_sync(0xffffffffu, sv, 2);
            sq += __shfl_xor_sync(0xffffffffu, sq, 2);
            if (qc == 0) {
                int r = mg * 32 + mt * 16 + half * 8 + g;
                *(float2*)&sm[(r * 2 + ng) * 2] = make_float2(sv, sq);
            }
        }
    __syncthreads();

#pragma unroll
    for (int mt = 0; mt < 2; mt++)
#pragma unroll
        for (int half = 0; half < 2; half++) {
            int r = mg * 32 + mt * 16 + half * 8 + g;
            float2 p0 = *(float2*)&sm[(r * 2 + 0) * 2];
            float2 p1 = *(float2*)&sm[(r * 2 + 1) * 2];
            float mu = (p0.x + p1.x) * (1.f / 64.f);
            float var = (p0.y + p1.y) * (1.f / 64.f) - mu * mu;
            float rstd = rsqrtf(var + 1e-5f);
            float* op = g_HLN + (size_t)(row0 + r) * FF;
#pragma unroll
            for (int j = 0; j < 4; j++) {
                int f0 = ((ng << 2) + j) * 8 + qc * 2;
                float2 o;
                o.x = (hc[mt][half][j * 2]     - mu) * rstd * sm[640 + f0]     + sm[704 + f0];
                o.y = (hc[mt][half][j * 2 + 1] - mu) * rstd * sm[640 + f0 + 1] + sm[704 + f0 + 1];
                *(float2*)(op + f0) = o;
            }
        }
}

// ---------------- final linear: out[b,c] = <HLN[b,:], lin_w[c,:]> + lin_b -----
__global__ void k_lin1(const float* __restrict__ w) {
    int chunk = blockIdx.x;
    int tid = threadIdx.x;
    int b = tid / CC, c = tid % CC;
    const float4* hp = (const float4*)(g_HLN + b * PERB + chunk * CHSZ);
    const float4* wp = (const float4*)(w     + c * PERB + chunk * CHSZ);
    float acc = 0.f;
#pragma unroll 4
    for (int i = 0; i < CHSZ / 4; i++) {
        float4 hv = hp[i], wv = wp[i];
        acc += hv.x * wv.x + hv.y * wv.y + hv.z * wv.z + hv.w * wv.w;
    }
    g_part[chunk * 160 + tid] = acc;
}
__global__ void __launch_bounds__(256) k_lin2(const float* __restrict__ lb, float* __restrict__ out) {
    __shared__ float red[256];
    int bc = blockIdx.x, t = threadIdx.x;
    float acc = 0.f;
    for (int ch = t; ch < NCHUNK; ch += 256) acc += g_part[ch * 160 + bc];
    red[t] = acc; __syncthreads();
#pragma unroll
    for (int o = 128; o; o >>= 1) {
        if (t < o) red[t] += red[t + o];
        __syncthreads();
    }
    if (t == 0) {
        int b = bc / CC, c = bc % CC;
        out[b * CC + c] = red[0] + lb[c];
    }
}

// ---------------- launch -------------------------------------------------------
extern "C" void kernel_launch(void* const* d_in, const int* in_sizes, int n_in,
                              void* d_out, int out_size) {
    const float* x    = (const float*)d_in[0];
    const int*   ei   = (const int*)  d_in[1];
    const float* Wz   = (const float*)d_in[2];
    const float* bz   = (const float*)d_in[3];
    // d_in[4], d_in[5] (W_r, b_r) are mathematically dead (h0 == 0)
    const float* Wh   = (const float*)d_in[6];
    const float* bh   = (const float*)d_in[7];
    const float* lng  = (const float*)d_in[8];
    const float* lnb  = (const float*)d_in[9];
    const float* lw   = (const float*)d_in[10];
    const float* lb   = (const float*)d_in[11];
    float* out = (float*)d_out;

    // idempotent, capture-safe, no static guards
    cudaFuncSetAttribute(k_gemm_mma, cudaFuncAttributeMaxDynamicSharedMemorySize, GSMEM);

    k_zero<<<4, 256>>>();
    k_count<<<(EE + 255) / 256, 256>>>(ei);
    k_scan<<<1, 1024>>>();
    k_fill<<<(EE + 255) / 256, 256>>>(ei);
    k_wcat<<<(KDIM * GDIM + 255) / 256, 256>>>(Wz, Wh);

    dim3 cb(32, 8);
    const int cg = (SS / 2) * NN / 8;      // 12000 blocks, warp = (node, snap-pair)
    k_cheb1<<<cg, cb>>>(x);                // term 0 + Tx1o + Tx1i
    k_cheb<<<cg, cb>>>(1, 5, 2, 6, 0);     // Tx2o, Tx2i  (sub Tx0)
    k_cheb<<<cg, cb>>>(2, 6, 3, 7, 1);     // Tx3o, Tx3i  (sub Tx1o)
    k_cheb<<<cg, cb>>>(3, 7, 4, 8, 2);     // Tx4o, Tx4i  (sub Tx2o)

    k_gemm_mma<<<RR / 128, 256, GSMEM>>>(bz, bh, lng, lnb);

    k_lin1<<<NCHUNK, 160>>>(lw);
    k_lin2<<<160, 256>>>(lb, out);
}

// round 16
// speedup vs baseline: 1.7485x; 1.1131x over previous
#include <cuda_runtime.h>
#include <math.h>
#include <cstdint>

#define NN 1000
#define FF 64
#define BB 16
#define TT 12
#define KK 5
#define CC 10
#define EE 16000
#define SS (BB*TT)          /* 192 snapshots */
#define RR (SS*NN)          /* 192000 rows   */
#define KDIM 576            /* 9 terms * 64  */
#define GDIM 128            /* 2 gates * 64  */
#define PERB (TT*NN*FF)     /* 768000        */
#define NCHUNK 1500
#define CHSZ 512

// GEMM tiling
#define KC    48
#define NCH   12
#define SAS   52            /* smem row stride (floats), 16B aligned */
#define TILEF (128*SAS)     /* 6656 floats per tile */
#define GSMEM (TILEF*4*4)   /* double-buffered A+B: 106496 bytes */

// ---------------- scratch (static device globals; no runtime alloc) ----------
__device__ float g_TX[RR * KDIM];        // 442 MB: 9 Chebyshev term blocks
__device__ float g_HLN[RR * FF];         // 49 MB: layernormed hidden
__device__ float g_Wt[GDIM * KDIM];      // fused weights, transposed
__device__ int   g_deg_out[NN], g_deg_in[NN];
__device__ float g_inv_out[NN], g_inv_in[NN];
__device__ int   g_in_ptr[NN + 1], g_out_ptr[NN + 1];
__device__ int2  g_in_ew[EE];            // {src_idx, weight-bits} packed
__device__ int   g_out_idx[EE];
__device__ int   g_cnt_in[NN], g_cnt_out[NN];
__device__ float g_part[NCHUNK * 160];

// ---------------- graph preprocessing ----------------------------------------
__global__ void k_zero() {
    int i = blockIdx.x * blockDim.x + threadIdx.x;
    if (i < NN) { g_deg_out[i] = 0; g_deg_in[i] = 0; g_cnt_in[i] = 0; g_cnt_out[i] = 0; }
}
__global__ void k_count(const int* __restrict__ ei) {
    int e = blockIdx.x * blockDim.x + threadIdx.x;
    if (e < EE) {
        atomicAdd(&g_deg_out[ei[e]], 1);
        atomicAdd(&g_deg_in[ei[EE + e]], 1);
    }
}
// parallel exclusive scan (1024 threads, Hillis-Steele in smem)
__global__ void __launch_bounds__(1024) k_scan() {
    __shared__ int sa[1024], sb[1024];
    int t = threadIdx.x;
    int a = (t < NN) ? g_deg_in[t]  : 0;
    int b = (t < NN) ? g_deg_out[t] : 0;
    sa[t] = a; sb[t] = b;
    __syncthreads();
    for (int o = 1; o < 1024; o <<= 1) {
        int va = (t >= o) ? sa[t - o] : 0;
        int vb = (t >= o) ? sb[t - o] : 0;
        __syncthreads();
        sa[t] += va; sb[t] += vb;
        __syncthreads();
    }
    if (t < NN) {
        g_in_ptr[t]  = sa[t] - a;       // exclusive
        g_out_ptr[t] = sb[t] - b;
        g_inv_in[t]  = 1.0f / (float)a;
        g_inv_out[t] = 1.0f / (float)b;
    }
    if (t == 0) { g_in_ptr[NN] = EE; g_out_ptr[NN] = EE; }
}
__global__ void k_fill(const int* __restrict__ ei) {
    int e = blockIdx.x * blockDim.x + threadIdx.x;
    if (e < EE) {
        int s = ei[e], d = ei[EE + e];
        int p = atomicAdd(&g_cnt_in[d], 1);
        g_in_ew[g_in_ptr[d] + p] = make_int2(s, __float_as_int(g_inv_out[s]));
        int q = atomicAdd(&g_cnt_out[s], 1);
        g_out_idx[g_out_ptr[s] + q] = d;
    }
}

// ---------------- fused weight build (transposed: g_Wt[n][k]) -----------------
__global__ void k_wcat(const float* __restrict__ Wz, const float* __restrict__ Wh) {
    int i = blockIdx.x * blockDim.x + threadIdx.x;
    if (i >= KDIM * GDIM) return;
    int col  = i / KDIM, krow = i % KDIM;
    int term = krow / FF, ic = krow % FF;
    int gate = col / FF,  oc = col % FF;
    const float* W = (gate == 0) ? Wz : Wh;
    float v;
    if (term == 0)
        v = W[((0 * KK + 0) * 2 * FF + ic) * FF + oc] +
            W[((1 * KK + 0) * 2 * FF + ic) * FF + oc];
    else if (term <= 4)
        v = W[((0 * KK + term) * 2 * FF + ic) * FF + oc];
    else
        v = W[((1 * KK + (term - 4)) * 2 * FF + ic) * FF + oc];
    g_Wt[col * KDIM + krow] = v;
}

// ------- Chebyshev: warp = (node, snapshot-pair); lane = float4 x half --------
__global__ void __launch_bounds__(256) k_cheb1(const float* __restrict__ x) {
    const int W = blockIdx.x * 8 + threadIdx.y;
    const int node = W % NN, qp = W / NN;
    const int lane = threadIdx.x;
    const int half = lane >> 4, col = (lane & 15) * 4;
    const int s = qp * 2 + half;
    const float* xs = x + (size_t)s * NN * FF + col;

    float4 aO = make_float4(0.f, 0.f, 0.f, 0.f);
    int jb = g_in_ptr[node], je = g_in_ptr[node + 1];
#pragma unroll 4
    for (int j = jb; j < je; j++) {
        int2 ew = g_in_ew[j];
        float w = __int_as_float(ew.y);
        float4 v = *(const float4*)(xs + (size_t)ew.x * FF);
        aO.x = fmaf(w, v.x, aO.x); aO.y = fmaf(w, v.y, aO.y);
        aO.z = fmaf(w, v.z, aO.z); aO.w = fmaf(w, v.w, aO.w);
    }
    float4 aI = make_float4(0.f, 0.f, 0.f, 0.f);
    jb = g_out_ptr[node]; je = g_out_ptr[node + 1];
#pragma unroll 4
    for (int j = jb; j < je; j++) {
        float4 v = *(const float4*)(xs + (size_t)g_out_idx[j] * FF);
        aI.x += v.x; aI.y += v.y; aI.z += v.z; aI.w += v.w;
    }
    float wi = g_inv_in[node];
    aI.x *= wi; aI.y *= wi; aI.z *= wi; aI.w *= wi;

    float4 x0 = *(const float4*)(xs + (size_t)node * FF);
    float* rp = g_TX + ((size_t)s * NN + node) * KDIM + col;
    *(float4*)(rp)           = x0;    // term 0
    *(float4*)(rp + 1 * FF)  = aO;    // Tx1o
    *(float4*)(rp + 5 * FF)  = aI;    // Tx1i
}

__global__ void __launch_bounds__(256) k_cheb(int so, int si, int dro, int dri, int sub) {
    const int W = blockIdx.x * 8 + threadIdx.y;
    const int node = W % NN, qp = W / NN;
    const int lane = threadIdx.x;
    const int half = lane >> 4, col = (lane & 15) * 4;
    const int s = qp * 2 + half;
    const size_t sb = (size_t)s * NN * KDIM;
    const float* bO = g_TX + sb + so * FF + col;
    const float* bI = g_TX + sb + si * FF + col;

    float4 aO = make_float4(0.f, 0.f, 0.f, 0.f);
    int jb = g_in_ptr[node], je = g_in_ptr[node + 1];
#pragma unroll 4
    for (int j = jb; j < je; j++) {
        int2 ew = g_in_ew[j];
        float w = __int_as_float(ew.y);
        float4 v = *(const float4*)(bO + (size_t)ew.x * KDIM);
        aO.x = fmaf(w, v.x, aO.x); aO.y = fmaf(w, v.y, aO.y);
        aO.z = fmaf(w, v.z, aO.z); aO.w = fmaf(w, v.w, aO.w);
    }
    float4 aI = make_float4(0.f, 0.f, 0.f, 0.f);
    jb = g_out_ptr[node]; je = g_out_ptr[node + 1];
#pragma unroll 4
    for (int j = jb; j < je; j++) {
        float4 v = *(const float4*)(bI + (size_t)g_out_idx[j] * KDIM);
        aI.x += v.x; aI.y += v.y; aI.z += v.z; aI.w += v.w;
    }
    float wi = g_inv_in[node];

    float* rp = g_TX + sb + (size_t)node * KDIM + col;
    float4 t0 = *(const float4*)(rp + sub * FF);
    aO.x = fmaf(2.f, aO.x, -t0.x); aO.y = fmaf(2.f, aO.y, -t0.y);
    aO.z = fmaf(2.f, aO.z, -t0.z); aO.w = fmaf(2.f, aO.w, -t0.w);
    aI.x = fmaf(2.f, aI.x * wi, -t0.x); aI.y = fmaf(2.f, aI.y * wi, -t0.y);
    aI.z = fmaf(2.f, aI.z * wi, -t0.z); aI.w = fmaf(2.f, aI.w * wi, -t0.w);
    *(float4*)(rp + dro * FF) = aO;
    *(float4*)(rp + dri * FF) = aI;
}

// ================= tf32 warp-MMA GEMM, double-buffered, fused epilogue ========
__device__ __forceinline__ uint32_t f2tf32(float f) {
    uint32_t r; asm("cvt.rna.tf32.f32 %0, %1;" : "=r"(r) : "f"(f)); return r;
}
__device__ __forceinline__ float4 cvt4(float4 v) {
    float4 r;
    r.x = __uint_as_float(f2tf32(v.x)); r.y = __uint_as_float(f2tf32(v.y));
    r.z = __uint_as_float(f2tf32(v.z)); r.w = __uint_as_float(f2tf32(v.w));
    return r;
}
#define MMA_TF32(c, a0, a1, a2, a3, b0, b1) \
    asm volatile("mma.sync.aligned.m16n8k8.row.col.f32.tf32.tf32.f32 " \
        "{%0,%1,%2,%3}, {%4,%5,%6,%7}, {%8,%9}, {%0,%1,%2,%3};" \
        : "+f"((c)[0]), "+f"((c)[1]), "+f"((c)[2]), "+f"((c)[3]) \
        : "r"(a0), "r"(a1), "r"(a2), "r"(a3), "r"(b0), "r"(b1))

__global__ void __launch_bounds__(256) k_gemm_mma(
    const float* __restrict__ bz, const float* __restrict__ bh,
    const float* __restrict__ lng, const float* __restrict__ lnb)
{
    extern __shared__ float sm[];
    const int tid = threadIdx.x, wid = tid >> 5, lane = tid & 31;
    const int mg = wid >> 1, ng = wid & 1, g = lane >> 2, qc = lane & 3;
    const int row0 = blockIdx.x * 128;

    float acc[2][8][4];
#pragma unroll
    for (int a = 0; a < 2; a++)
#pragma unroll
        for (int j = 0; j < 8; j++)
#pragma unroll
            for (int d = 0; d < 4; d++) acc[a][j][d] = 0.f;

    const int rr = tid >> 1, hh = tid & 1;
    const float* Ag = g_TX + (size_t)(row0 + rr) * KDIM + hh * 24;
    const float* Bg = g_Wt + (size_t)rr * KDIM + hh * 24;
    float4 pa[6], pb[6];

#pragma unroll
    for (int i = 0; i < 6; i++) {
        pa[i] = *(const float4*)(Ag + i * 4);
        pb[i] = *(const float4*)(Bg + i * 4);
    }
#pragma unroll
    for (int i = 0; i < 6; i++) {
        *(float4*)&sm[rr * SAS + hh * 24 + i * 4]          = cvt4(pa[i]);
        *(float4*)&sm[TILEF + rr * SAS + hh * 24 + i * 4]  = cvt4(pb[i]);
    }
#pragma unroll
    for (int i = 0; i < 6; i++) {
        pa[i] = *(const float4*)(Ag + KC + i * 4);
        pb[i] = *(const float4*)(Bg + KC + i * 4);
    }
    __syncthreads();

#pragma unroll 1
    for (int ch = 0; ch < NCH; ch++) {
        const int cur = ch & 1, nxt = cur ^ 1;
        float* sA = sm + cur * 2 * TILEF;
        float* sB = sA + TILEF;
        if (ch + 1 < NCH) {
            float* dA = sm + nxt * 2 * TILEF;
#pragma unroll
            for (int i = 0; i < 6; i++) {
                *(float4*)&dA[rr * SAS + hh * 24 + i * 4]         = cvt4(pa[i]);
                *(float4*)&dA[TILEF + rr * SAS + hh * 24 + i * 4] = cvt4(pb[i]);
            }
        }
        if (ch + 2 < NCH) {
#pragma unroll
            for (int i = 0; i < 6; i++) {
                pa[i] = *(const float4*)(Ag + (ch + 2) * KC + i * 4);
                pb[i] = *(const float4*)(Bg + (ch + 2) * KC + i * 4);
            }
        }
#pragma unroll
        for (int ks = 0; ks < 6; ks++) {
            const int k0 = ks * 8;
            uint32_t a[2][4];
#pragma unroll
            for (int mt = 0; mt < 2; mt++) {
                int r = mg * 32 + mt * 16 + g;
                a[mt][0] = __float_as_uint(sA[r * SAS + k0 + qc]);
                a[mt][1] = __float_as_uint(sA[(r + 8) * SAS + k0 + qc]);
                a[mt][2] = __float_as_uint(sA[r * SAS + k0 + qc + 4]);
                a[mt][3] = __float_as_uint(sA[(r + 8) * SAS + k0 + qc + 4]);
            }
#pragma unroll
            for (int j = 0; j < 8; j++) {
                int ntg = ((j >> 2) << 3) + (ng << 2) + (j & 3);
                int col = ntg * 8 + g;
                uint32_t b0 = __float_as_uint(sB[col * SAS + k0 + qc]);
                uint32_t b1 = __float_as_uint(sB[col * SAS + k0 + qc + 4]);
                MMA_TF32(acc[0][j], a[0][0], a[0][1], a[0][2], a[0][3], b0, b1);
                MMA_TF32(acc[1][j], a[1][0], a[1][1], a[1][2], a[1][3], b0, b1);
            }
        }
        __syncthreads();
    }

    if (tid < 64) {
        sm[512 + tid] = bz[tid];
        sm[576 + tid] = bh[tid];
        sm[640 + tid] = lng[tid];
        sm[704 + tid] = lnb[tid];
    }
    __syncthreads();

    float hc[2][2][8];
#pragma unroll
    for (int mt = 0; mt < 2; mt++)
#pragma unroll
        for (int half = 0; half < 2; half++) {
            float sv = 0.f, sq = 0.f;
#pragma unroll
            for (int j = 0; j < 4; j++)
#pragma unroll
                for (int d = 0; d < 2; d++) {
                    int fz = ((ng << 2) + j) * 8 + qc * 2 + d;
                    float zl = acc[mt][j][half * 2 + d]     + sm[512 + fz];
                    float hl = acc[mt][j + 4][half * 2 + d] + sm[576 + fz];
                    float z  = 1.f / (1.f + __expf(-zl));
                    float v  = fmaxf((1.f - z) * tanhf(hl), 0.f);
                    hc[mt][half][j * 2 + d] = v;
                    sv += v; sq += v * v;
                }
            sv += __shfl_xor_sync(0xffffffffu, sv, 1);
            sq += __shfl_xor_sync(0xffffffffu, sq, 1);
            sv += __shfl_xor_sync(0xffffffffu, sv, 2);
            sq += __shfl_xor_sync(0xffffffffu, sq, 2);
            if (qc == 0) {
                int r = mg * 32 + mt * 16 + half * 8 + g;
                *(float2*)&sm[(r * 2 + ng) * 2] = make_float2(sv, sq);
            }
        }
    __syncthreads();

#pragma unroll
    for (int mt = 0; mt < 2; mt++)
#pragma unroll
        for (int half = 0; half < 2; half++) {
            int r = mg * 32 + mt * 16 + half * 8 + g;
            float2 p0 = *(float2*)&sm[(r * 2 + 0) * 2];
            float2 p1 = *(float2*)&sm[(r * 2 + 1) * 2];
            float mu = (p0.x + p1.x) * (1.f / 64.f);
            float var = (p0.y + p1.y) * (1.f / 64.f) - mu * mu;
            float rstd = rsqrtf(var + 1e-5f);
            float* op = g_HLN + (size_t)(row0 + r) * FF;
#pragma unroll
            for (int j = 0; j < 4; j++) {
                int f0 = ((ng << 2) + j) * 8 + qc * 2;
                float2 o;
                o.x = (hc[mt][half][j * 2]     - mu) * rstd * sm[640 + f0]     + sm[704 + f0];
                o.y = (hc[mt][half][j * 2 + 1] - mu) * rstd * sm[640 + f0 + 1] + sm[704 + f0 + 1];
                *(float2*)(op + f0) = o;
            }
        }
}

// ---------------- final linear: out[b,c] = <HLN[b,:], lin_w[c,:]> + lin_b -----
__global__ void k_lin1(const float* __restrict__ w) {
    int chunk = blockIdx.x;
    int tid = threadIdx.x;
    int b = tid / CC, c = tid % CC;
    const float4* hp = (const float4*)(g_HLN + b * PERB + chunk * CHSZ);
    const float4* wp = (const float4*)(w     + c * PERB + chunk * CHSZ);
    float acc = 0.f;
#pragma unroll 4
    for (int i = 0; i < CHSZ / 4; i++) {
        float4 hv = hp[i], wv = wp[i];
        acc += hv.x * wv.x + hv.y * wv.y + hv.z * wv.z + hv.w * wv.w;
    }
    g_part[chunk * 160 + tid] = acc;
}
__global__ void __launch_bounds__(256) k_lin2(const float* __restrict__ lb, float* __restrict__ out) {
    __shared__ float red[256];
    int bc = blockIdx.x, t = threadIdx.x;
    float acc = 0.f;
    for (int ch = t; ch < NCHUNK; ch += 256) acc += g_part[ch * 160 + bc];
    red[t] = acc; __syncthreads();
#pragma unroll
    for (int o = 128; o; o >>= 1) {
        if (t < o) red[t] += red[t + o];
        __syncthreads();
    }
    if (t == 0) {
        int b = bc / CC, c = bc % CC;
        out[b * CC + c] = red[0] + lb[c];
    }
}

// ---------------- launch -------------------------------------------------------
extern "C" void kernel_launch(void* const* d_in, const int* in_sizes, int n_in,
                              void* d_out, int out_size) {
    const float* x    = (const float*)d_in[0];
    const int*   ei   = (const int*)  d_in[1];
    const float* Wz   = (const float*)d_in[2];
    const float* bz   = (const float*)d_in[3];
    // d_in[4], d_in[5] (W_r, b_r) are mathematically dead (h0 == 0)
    const float* Wh   = (const float*)d_in[6];
    const float* bh   = (const float*)d_in[7];
    const float* lng  = (const float*)d_in[8];
    const float* lnb  = (const float*)d_in[9];
    const float* lw   = (const float*)d_in[10];
    const float* lb   = (const float*)d_in[11];
    float* out = (float*)d_out;

    // idempotent, capture-safe, no static guards
    cudaFuncSetAttribute(k_gemm_mma, cudaFuncAttributeMaxDynamicSharedMemorySize, GSMEM);

    k_zero<<<4, 256>>>();
    k_count<<<(EE + 255) / 256, 256>>>(ei);
    k_scan<<<1, 1024>>>();
    k_fill<<<(EE + 255) / 256, 256>>>(ei);
    k_wcat<<<(KDIM * GDIM + 255) / 256, 256>>>(Wz, Wh);

    dim3 cb(32, 8);
    const int cg = (SS / 2) * NN / 8;      // 12000 blocks, warp = (node, snap-pair)
    k_cheb1<<<cg, cb>>>(x);                // term 0 + Tx1o + Tx1i
    k_cheb<<<cg, cb>>>(1, 5, 2, 6, 0);     // Tx2o, Tx2i  (sub Tx0)
    k_cheb<<<cg, cb>>>(2, 6, 3, 7, 1);     // Tx3o, Tx3i  (sub Tx1o)
    k_cheb<<<cg, cb>>>(3, 7, 4, 8, 2);     // Tx4o, Tx4i  (sub Tx2o)

    k_gemm_mma<<<RR / 128, 256, GSMEM>>>(bz, bh, lng, lnb);

    k_lin1<<<NCHUNK, 160>>>(lw);
    k_lin2<<<160, 256>>>(lb, out);
}